// round 15
// baseline (speedup 1.0000x reference)
#include <cuda_runtime.h>
#include <cuda_fp16.h>

#define N 4096
#define D 512
#define NCLASS 100
#define GRID 296
#define THREADS 256
#define MAXG 640

__device__ __half g_zh[N * D];     // normalized z, fp16
__device__ float g_eadv[N];        // exp(cos(z, z_adv)/T)
__device__ int   g_count[NCLASS];
__device__ int   g_offset[NCLASS];
__device__ int   g_members[N];     // row indices grouped by class (stable)
__device__ int   g_sl[N];          // decoded labels (sort scratch)
__device__ int   g_grp_class[MAXG];
__device__ int   g_grp_k8[MAXG];
__device__ int   g_ngroups;
__device__ float g_partial[GRID];
__device__ unsigned int g_done;
__device__ unsigned int g_bar_count;
__device__ volatile unsigned int g_bar_gen;

__constant__ float c_invT = 2.0f;  // 1 / TEMPERATURE
__constant__ float c_eps  = 1e-8f;

// generation grid barrier: GRID=296 = 2 blocks/SM co-resident. Ordering-only.
__device__ __forceinline__ void grid_sync() {
    __syncthreads();
    if (threadIdx.x == 0) {
        unsigned int mygen = g_bar_gen;
        __threadfence();
        unsigned int old = atomicAdd(&g_bar_count, 1u);
        if (old == GRID - 1) {
            g_bar_count = 0;
            __threadfence();
            g_bar_gen = mygen + 1;
        } else {
            while (g_bar_gen == mygen) __nanosleep(64);
        }
        __threadfence();
    }
    __syncthreads();
}

__global__ void __launch_bounds__(THREADS, 2)
k_all(const float* __restrict__ z, const float* __restrict__ za,
      const int* __restrict__ lab, float* __restrict__ out) {
    // Phase-B tiles (47.2 KB static total, under the 48 KB static limit)
    __shared__ uint4 sJ[32][65];       // 33.3 KB member tile (row pad -> 4-bank shift)
    __shared__ uint4 sA[8][65];        // 8.3 KB i-rows of this group
    __shared__ int   sJid[32];
    __shared__ int   sIid[8];
    __shared__ float part[8][8];
    __shared__ float lossv[8];
    __shared__ float s_block_loss;
    __shared__ float smr[THREADS];     // final reduction
    // sort scratch (block 0)
    __shared__ int whist[8][NCLASS];
    __shared__ int cls_cnt[NCLASS];
    __shared__ int cls_off[NCLASS];
    __shared__ int pgo[NCLASS];
    __shared__ int ok;
    __shared__ bool is_last;

    int t = threadIdx.x;
    int lane = t & 31, w = t >> 5;

    // ================= Phase A: normalize (row-strided over all warps) =====
    for (int row = blockIdx.x * 8 + w; row < N; row += GRID * 8) {
        const float4* zr  = reinterpret_cast<const float4*>(z  + (size_t)row * D);
        const float4* zar = reinterpret_cast<const float4*>(za + (size_t)row * D);
        float4 v[4], u[4];
#pragma unroll
        for (int k = 0; k < 4; k++) { v[k] = zr[lane + 32 * k]; u[k] = zar[lane + 32 * k]; }
        float sz = 0.0f, sa = 0.0f, dd = 0.0f;
#pragma unroll
        for (int k = 0; k < 4; k++) {
            sz += v[k].x * v[k].x + v[k].y * v[k].y + v[k].z * v[k].z + v[k].w * v[k].w;
            sa += u[k].x * u[k].x + u[k].y * u[k].y + u[k].z * u[k].z + u[k].w * u[k].w;
            dd += v[k].x * u[k].x + v[k].y * u[k].y + v[k].z * u[k].z + v[k].w * u[k].w;
        }
#pragma unroll
        for (int o = 16; o; o >>= 1) {
            sz += __shfl_xor_sync(0xffffffffu, sz, o);
            sa += __shfl_xor_sync(0xffffffffu, sa, o);
            dd += __shfl_xor_sync(0xffffffffu, dd, o);
        }
        float invz  = 1.0f / fmaxf(sqrtf(sz), c_eps);
        float invza = 1.0f / fmaxf(sqrtf(sa), c_eps);
#pragma unroll
        for (int k = 0; k < 4; k++) {
            __half2 h0 = __floats2half2_rn(v[k].x * invz, v[k].y * invz);
            __half2 h1 = __floats2half2_rn(v[k].z * invz, v[k].w * invz);
            uint2 packed = make_uint2(*reinterpret_cast<unsigned*>(&h0),
                                      *reinterpret_cast<unsigned*>(&h1));
            reinterpret_cast<uint2*>(g_zh + (size_t)row * D)[lane + 32 * k] = packed;
        }
        if (lane == 0) g_eadv[row] = expf(dd * invz * invza * c_invT);
    }

    // ================= Phase A': label sort + group table (block 0) ========
    if (blockIdx.x == 0) {
        if (t == 0) { ok = 1; g_done = 0u; }
        __syncthreads();
        bool good = true;
        for (int k = t; k < N / 2; k += THREADS) {
            int lo = lab[2 * k];
            int hi = lab[2 * k + 1];
            if (hi != 0 || lo < 0 || lo >= NCLASS) good = false;
        }
        if (!good) atomicExch(&ok, 0);
        __syncthreads();
        int is64 = ok;

        for (int i = t; i < N; i += THREADS) g_sl[i] = is64 ? lab[2 * i] : lab[i];
        for (int c = lane; c < NCLASS; c += 32) whist[w][c] = 0;
        __syncthreads();

        int rbase = w * 512;
#pragma unroll 1
        for (int it = 0; it < 16; it++) {
            int c = g_sl[rbase + it * 32 + lane];
            unsigned mask = __match_any_sync(0xffffffffu, c);
            int leader = __ffs(mask) - 1;
            if (lane == leader) whist[w][c] += __popc(mask);
            __syncwarp();
        }
        __syncthreads();

        if (t < NCLASS) {
            int run = 0;
#pragma unroll
            for (int k = 0; k < 8; k++) {
                int v = whist[k][t];
                whist[k][t] = run;
                run += v;
            }
            cls_cnt[t] = run;
        }
        __syncthreads();

        if (w == 0) {   // class offsets
            int carry = 0;
#pragma unroll
            for (int seg = 0; seg < 4; seg++) {
                int c = seg * 32 + lane;
                int v = (c < NCLASS) ? cls_cnt[c] : 0;
                int inc = v;
#pragma unroll
                for (int o = 1; o < 32; o <<= 1) {
                    int y = __shfl_up_sync(0xffffffffu, inc, o);
                    if (lane >= o) inc += y;
                }
                if (c < NCLASS) cls_off[c] = inc - v + carry;
                carry += __shfl_sync(0xffffffffu, inc, 31);
            }
        }
        if (w == 1) {   // padded-group offsets (concurrent with warp 0)
            int carry = 0;
#pragma unroll
            for (int seg = 0; seg < 4; seg++) {
                int c = seg * 32 + lane;
                int ngc = 0;  // needs cls_cnt: written pre-sync above
                if (c < NCLASS) ngc = (cls_cnt[c] + 7) >> 3;
                int inc = ngc;
#pragma unroll
                for (int o = 1; o < 32; o <<= 1) {
                    int y = __shfl_up_sync(0xffffffffu, inc, o);
                    if (lane >= o) inc += y;
                }
                if (c < NCLASS) pgo[c] = inc - ngc + carry;
                carry += __shfl_sync(0xffffffffu, inc, 31);
            }
            if (lane == 0) g_ngroups = carry;
        }
        __syncthreads();

        // group table
        if (t < NCLASS) {
            int base = pgo[t];
            int ngc = (cls_cnt[t] + 7) >> 3;
            for (int k = 0; k < ngc; k++) {
                g_grp_class[base + k] = t;
                g_grp_k8[base + k] = k << 3;
            }
        }

        // stable emit
#pragma unroll 1
        for (int it = 0; it < 16; it++) {
            int row = rbase + it * 32 + lane;
            int c = g_sl[row];
            unsigned mask = __match_any_sync(0xffffffffu, c);
            int rank = __popc(mask & ((1u << lane) - 1u));
            int base = whist[w][c];
            g_members[cls_off[c] + base + rank] = row;
            int leader = __ffs(mask) - 1;
            if (lane == leader) whist[w][c] = base + __popc(mask);
            __syncwarp();
        }
        if (t < NCLASS) { g_count[t] = cls_cnt[t]; g_offset[t] = cls_off[t]; }
    }

    // ================= grid barrier =================
    grid_sync();

    // ================= Phase B: GEMM-shaped intra (lane = one pair) ========
    if (t == 0) s_block_loss = 0.0f;
    __syncthreads();
    int ngroups = g_ngroups;
    int i_q = lane >> 2;           // 0..7: which i-row of the group
    int jt  = w * 4 + (lane & 3);  // 0..31: which member of the tile

    for (int g = blockIdx.x; g < ngroups; g += GRID) {
        int c = g_grp_class[g];
        int k8 = g_grp_k8[g];
        int off = g_offset[c];
        int cnt = g_count[c];
        int n_i = min(8, cnt - k8);

        // stage group's 8 i-rows (clamped) + their row ids
        if (t < 8) sIid[t] = g_members[off + k8 + min(t, n_i - 1)];
        {
            int q = t >> 5, u = t & 31;
            int irow = g_members[off + k8 + min(q, n_i - 1)];
            const uint4* rp = reinterpret_cast<const uint4*>(g_zh + (size_t)irow * D);
            sA[q][u] = rp[u];
            sA[q][u + 32] = rp[u + 32];
        }
        __syncthreads();
        int myIid = sIid[i_q];

        float acc = 0.0f;
        for (int tb = 0; tb < cnt; tb += 32) {
            // cooperative tile load: 32 member rows (clamped), 128B segments
            {
                int jr = t >> 3, kk = t & 7;
                int m = min(tb + jr, cnt - 1);
                int jrow = g_members[off + m];
                if (kk == 0) sJid[jr] = jrow;
                const uint4* rp = reinterpret_cast<const uint4*>(g_zh + (size_t)jrow * D);
#pragma unroll
                for (int x = 0; x < 8; x++) sJ[jr][kk + 8 * x] = rp[kk + 8 * x];
            }
            __syncthreads();

            // per-lane 512-dim dot, conflict-free smem, no shuffles
            float dot = 0.0f;
#pragma unroll 8
            for (int d = 0; d < 64; d++) {
                uint4 ua = sA[i_q][d];
                uint4 uj = sJ[jt][d];
                const __half2* A = reinterpret_cast<const __half2*>(&ua);
                const __half2* J = reinterpret_cast<const __half2*>(&uj);
                __half2 h = __hmul2(A[0], J[0]);
                h = __hfma2(A[1], J[1], h);
                h = __hfma2(A[2], J[2], h);
                h = __hfma2(A[3], J[3], h);
                float2 f = __half22float2(h);
                dot += f.x + f.y;
            }
            int m2 = tb + jt;
            bool valid = (m2 < cnt) && (sJid[jt] != myIid);
            acc += valid ? __expf(dot * c_invT) : 0.0f;
            __syncthreads();
        }

        // quad reduce (lanes 4q..4q+3 share i-row q)
        acc += __shfl_xor_sync(0xffffffffu, acc, 1);
        acc += __shfl_xor_sync(0xffffffffu, acc, 2);
        if ((lane & 3) == 0) part[w][i_q] = acc;
        __syncthreads();
        if (t < 8) {
            float s = 0.0f;
#pragma unroll
            for (int ww = 0; ww < 8; ww++) s += part[ww][t];
            lossv[t] = (t < n_i) ? log1pf(s / g_eadv[sIid[t]]) : 0.0f;
        }
        __syncthreads();
        if (t == 0) {
            float bs = 0.0f;
#pragma unroll
            for (int q = 0; q < 8; q++) bs += lossv[q];
            s_block_loss += bs;
        }
        __syncthreads();
    }

    // ================= Phase C: ticketed final reduction =================
    if (t == 0) {
        g_partial[blockIdx.x] = s_block_loss;
        __threadfence();
        unsigned int ticket = atomicAdd(&g_done, 1u);
        is_last = (ticket == GRID - 1);
    }
    __syncthreads();

    if (is_last) {
        __threadfence();
        smr[t] = g_partial[t] + ((t + THREADS < GRID) ? g_partial[t + THREADS] : 0.0f);
        __syncthreads();
#pragma unroll
        for (int o = THREADS / 2; o > 0; o >>= 1) {
            if (t < o) smr[t] += smr[t + o];
            __syncthreads();
        }
        if (t == 0) out[0] = smr[0] * (1.0f / (float)N);
    }
}

extern "C" void kernel_launch(void* const* d_in, const int* in_sizes, int n_in,
                              void* d_out, int out_size) {
    const float* z   = (const float*)d_in[0];
    const float* za  = (const float*)d_in[1];
    const int*   lab = (const int*)d_in[2];
    float* out = (float*)d_out;

    k_all<<<GRID, THREADS>>>(z, za, lab, out);
}